// round 13
// baseline (speedup 1.0000x reference)
#include <cuda_runtime.h>

#define NROWS 8192
#define CCOLS 2048
#define BINS  30
#define TOTF  8192.0f   /* tot = max(N,1) */

/* K1 tiling */
#define TPB1  128       /* threads = columns per block */
#define RPB1  64        /* rows per block */
#define YBLK  (NROWS / RPB1)   /* 128 row-chunk slabs */

// Scratch (no cudaMalloc allowed). Referenced ONLY from device code.
__device__ unsigned short g_pcnt[YBLK * BINS * CCOLS];  // 15.7 MB count slabs (atomic-free)
__device__ unsigned int   g_bits[NROWS * (CCOLS / 32)]; // 2 MB packed targets
__device__ float          g_wfac[BINS * CCOLS];         // 245 KB weight table

// bin = clip(floor(30*|sigmoid(p)-t|), 0, 29)
// |sigmoid(p)-t| = sigmoid(s), s = p*(1-2t) for t in {0,1}  (s = +/-p exactly)
// 30*sigmoid(s) = 15*tanh(s/2) + 15  -> single MUFU.TANH, deterministic:
// identical s in K1 and K3 yields identical bin, so K3 only gathers counted bins.
__device__ __forceinline__ int bin_of_s(float s) {
    float u;
    asm("tanh.approx.f32 %0, %1;" : "=f"(u) : "f"(0.5f * s));
    int b = __float2int_rd(fmaf(15.0f, u, 15.0f));
    return min(max(b, 0), BINS - 1);
}

// ---------------------------------------------------------------- K1: histogram + bit-pack
// Count-only pass. Each thread owns one column; u16 shared counters (7.7 KB ->
// ~high occupancy). Targets packed into a bit-matrix with one ballot per
// warp-row. Flush = private slab store, no atomics, no __syncthreads.
__global__ __launch_bounds__(TPB1) void hist_kernel(const float* __restrict__ preds,
                                                    const int*   __restrict__ targets) {
    __shared__ unsigned short sh[BINS][TPB1];   // 7680 B
    const int tid  = threadIdx.x;
    const int lane = tid & 31;
    const int wid  = tid >> 5;
    const int c    = blockIdx.x * TPB1 + tid;
    const int r0   = blockIdx.y * RPB1;

#pragma unroll
    for (int b = 0; b < BINS; b++) sh[b][tid] = 0;
    // no __syncthreads: each thread only touches sh[*][tid]

    const float* pp = preds   + (size_t)r0 * CCOLS + c;
    const int*   tp = targets + (size_t)r0 * CCOLS + c;
    const int wordcol = blockIdx.x * (TPB1 / 32) + wid;   // which 32-col word

#pragma unroll 8
    for (int r = 0; r < RPB1; r++) {
        float p  = pp[(size_t)r * CCOLS];
        int   ti = tp[(size_t)r * CCOLS];
        float s = p * fmaf(-2.0f, (float)ti, 1.0f);
        int   b = bin_of_s(s);
        sh[b][tid]++;
        unsigned int w = __ballot_sync(0xffffffffu, ti);
        if (lane == 0) g_bits[(size_t)(r0 + r) * (CCOLS / 32) + wordcol] = w;
    }

    // flush: coalesced u16 stores into this row-chunk's private slab
    const size_t base = (size_t)blockIdx.y * (BINS * CCOLS) + c;
#pragma unroll
    for (int b = 0; b < BINS; b++) g_pcnt[base + b * CCOLS] = sh[b][tid];
}

// ---------------------------------------------------------------- K2: fold weight table
// wfac[b][c] = TOT / (0.75*acc[b][c] + 0.25*cnt[b][c]) / max(n_c,1)
// (inf for empty bins with acc=0 — harmless: K3 never gathers uncounted bins)
__global__ __launch_bounds__(256) void wfac_kernel(const float* __restrict__ acc_sum,
                                                   float* __restrict__ out) {
    const int c = blockIdx.x * 256 + threadIdx.x;
    if (c == 0) out[0] = 0.0f;

    int counts[BINS];
#pragma unroll
    for (int b = 0; b < BINS; b++) counts[b] = 0;

#pragma unroll 2
    for (int y = 0; y < YBLK; y++) {
        const size_t base = (size_t)y * (BINS * CCOLS) + c;
#pragma unroll
        for (int b = 0; b < BINS; b++) counts[b] += (int)g_pcnt[base + b * CCOLS];
    }

    int n = 0;
#pragma unroll
    for (int b = 0; b < BINS; b++) n += (counts[b] >= 1) ? 1 : 0;
    float nf = (float)max(n, 1);

#pragma unroll
    for (int b = 0; b < BINS; b++) {
        float accn = fmaf(0.25f, (float)counts[b], 0.75f * acc_sum[b * CCOLS + c]);
        g_wfac[b * CCOLS + c] = TOTF / (accn * nf);
    }
}

// ---------------------------------------------------------------- K3: weighted BCE sum
// Reads preds (64 MB) + packed target bits (2 MB) + wfac table (L2-resident).
__device__ __forceinline__ float elem_term(float p, int tbit, int c) {
    float t = (float)tbit;
    float s = p * fmaf(-2.0f, t, 1.0f);           // bce = softplus(s)
    int   b = bin_of_s(s);                        // identical math as K1
    float w = __ldg(&g_wfac[b * CCOLS + c]);      // 245 KB table, L2-resident
    float e   = __expf(-fabsf(s));
    float bce = fmaxf(s, 0.0f) + __logf(1.0f + e);
    return w * bce;
}

__global__ __launch_bounds__(256) void loss_kernel(const float4* __restrict__ preds,
                                                   float* __restrict__ out,
                                                   int nvec, float scale) {
    float acc = 0.0f;
    const int stride = gridDim.x * blockDim.x;
    for (int v = blockIdx.x * blockDim.x + threadIdx.x; v < nvec; v += stride) {
        float4 p = preds[v];
        int c = (v * 4) & (CCOLS - 1);            // 512 float4 per row
        int r = v >> 9;
        unsigned int w = g_bits[(size_t)r * (CCOLS / 32) + (c >> 5)];
        int sh_ = c & 31;                          // c%4==0 -> bits never straddle
        acc += elem_term(p.x, (w >> (sh_ + 0)) & 1, c + 0);
        acc += elem_term(p.y, (w >> (sh_ + 1)) & 1, c + 1);
        acc += elem_term(p.z, (w >> (sh_ + 2)) & 1, c + 2);
        acc += elem_term(p.w, (w >> (sh_ + 3)) & 1, c + 3);
    }
    // block reduction -> one atomic per block
#pragma unroll
    for (int o = 16; o > 0; o >>= 1) acc += __shfl_down_sync(0xffffffffu, acc, o);
    __shared__ float sw[8];
    int lane = threadIdx.x & 31, wid = threadIdx.x >> 5;
    if (lane == 0) sw[wid] = acc;
    __syncthreads();
    if (wid == 0) {
        acc = (lane < 8) ? sw[lane] : 0.0f;
#pragma unroll
        for (int o = 4; o > 0; o >>= 1) acc += __shfl_down_sync(0xffffffffu, acc, o);
        if (lane == 0) atomicAdd(out, acc * scale);
    }
}

// ---------------------------------------------------------------- launch
extern "C" void kernel_launch(void* const* d_in, const int* in_sizes, int n_in,
                              void* d_out, int out_size) {
    const float* preds   = (const float*)d_in[0];   // [8192, 2048] f32
    const int*   targets = (const int*)  d_in[1];   // [8192, 2048] i32
    const float* acc_sum = (const float*)d_in[2];   // [30, 2048]   f32
    float* out = (float*)d_out;                     // scalar loss

    // K1: count histogram + target bit-pack (16 col-tiles x 128 row-chunks = 2048 blocks)
    dim3 hgrid(CCOLS / TPB1, NROWS / RPB1);
    hist_kernel<<<hgrid, TPB1>>>(preds, targets);

    // K2: fold slabs -> weight table, zero out
    wfac_kernel<<<CCOLS / 256, 256>>>(acc_sum, out);

    // K3: weighted BCE mean (preds + bit matrix, globals referenced device-side)
    const int nvec = (NROWS * CCOLS) / 4;
    const float scale = 1.0f / ((float)NROWS * (float)CCOLS);  // LOSS_WEIGHT = 1
    loss_kernel<<<1184, 256>>>((const float4*)preds, out, nvec, scale);
}

// round 15
// speedup vs baseline: 2.7275x; 2.7275x over previous
#include <cuda_runtime.h>

#define NROWS 8192
#define CCOLS 2048
#define BINS  30
#define TOTF  8192.0f   /* tot = max(N,1) */
#define NCELL (BINS * CCOLS)   /* 61440 */

/* K1 tiling */
#define TPB1  128       /* threads = columns per block */
#define RPB1  64        /* rows per block */
#define YBLK  (NROWS / RPB1)   /* 128 row-chunk slabs */

// Scratch (no cudaMalloc allowed). Referenced ONLY from device code.
__device__ unsigned short g_pcnt[YBLK * NCELL];         // 15.7 MB count slabs (atomic-free)
__device__ unsigned int   g_bits[NROWS * (CCOLS / 32)]; // 2 MB packed targets
__device__ int            g_cnt[NCELL];                 // 245 KB folded counts
__device__ float          g_wfac[NCELL];                // 245 KB weight table

// bin = clip(floor(30*|sigmoid(p)-t|), 0, 29)
// |sigmoid(p)-t| = sigmoid(s), s = p*(1-2t) for t in {0,1}  (s = +/-p exactly)
// 30*sigmoid(s) = 15*tanh(s/2) + 15  -> single MUFU.TANH, deterministic:
// identical s in K1 and K3 yields identical bin, so K3 only gathers counted bins.
__device__ __forceinline__ int bin_of_s(float s) {
    float u;
    asm("tanh.approx.f32 %0, %1;" : "=f"(u) : "f"(0.5f * s));
    int b = __float2int_rd(fmaf(15.0f, u, 15.0f));
    return min(max(b, 0), BINS - 1);
}

// ---------------------------------------------------------------- K1: histogram + bit-pack
// Count-only pass. Each thread owns one column; u16 shared counters (7.7 KB ->
// ~14 blocks/SM, 87% occ). Targets packed into a bit-matrix with one ballot per
// warp-row. Flush = private slab store, no atomics, no __syncthreads.
__global__ __launch_bounds__(TPB1) void hist_kernel(const float* __restrict__ preds,
                                                    const int*   __restrict__ targets) {
    __shared__ unsigned short sh[BINS][TPB1];   // 7680 B
    const int tid  = threadIdx.x;
    const int lane = tid & 31;
    const int wid  = tid >> 5;
    const int c    = blockIdx.x * TPB1 + tid;
    const int r0   = blockIdx.y * RPB1;

#pragma unroll
    for (int b = 0; b < BINS; b++) sh[b][tid] = 0;
    // no __syncthreads: each thread only touches sh[*][tid]

    const float* pp = preds   + (size_t)r0 * CCOLS + c;
    const int*   tp = targets + (size_t)r0 * CCOLS + c;
    const int wordcol = blockIdx.x * (TPB1 / 32) + wid;   // which 32-col word

#pragma unroll 8
    for (int r = 0; r < RPB1; r++) {
        float p  = pp[(size_t)r * CCOLS];
        int   ti = tp[(size_t)r * CCOLS];
        float s = p * fmaf(-2.0f, (float)ti, 1.0f);
        int   b = bin_of_s(s);
        sh[b][tid]++;
        unsigned int w = __ballot_sync(0xffffffffu, ti);
        if (lane == 0) g_bits[(size_t)(r0 + r) * (CCOLS / 32) + wordcol] = w;
    }

    // flush: coalesced u16 stores into this row-chunk's private slab
    const size_t base = (size_t)blockIdx.y * NCELL + c;
#pragma unroll
    for (int b = 0; b < BINS; b++) g_pcnt[base + b * CCOLS] = sh[b][tid];
}

// ---------------------------------------------------------------- K2a: fold slabs (chip-wide)
// Each thread folds TWO cells via one uint load per slab (coalesced 128B/warp).
// 30720 threads = 120 blocks. Also zeroes out[0].
__global__ __launch_bounds__(256) void reduce_kernel(float* __restrict__ out) {
    const int j = blockIdx.x * 256 + threadIdx.x;   // j < NCELL/2
    if (j == 0) out[0] = 0.0f;
    const unsigned int* src = (const unsigned int*)g_pcnt;
    unsigned int lo = 0, hi = 0;
#pragma unroll 16
    for (int y = 0; y < YBLK; y++) {
        unsigned int v = src[(size_t)y * (NCELL / 2) + j];
        lo += v & 0xffffu;
        hi += v >> 16;
    }
    g_cnt[2 * j]     = (int)lo;
    g_cnt[2 * j + 1] = (int)hi;
}

// ---------------------------------------------------------------- K2b: weight table
// wfac[b][c] = TOT / (0.75*acc[b][c] + 0.25*cnt[b][c]) / max(n_c,1)
// Reads only 245 KB (L2-hot after K2a). inf for empty bins is harmless:
// K3 never gathers uncounted bins.
__global__ __launch_bounds__(256) void wfac_kernel(const float* __restrict__ acc_sum) {
    const int c = blockIdx.x * 256 + threadIdx.x;

    int counts[BINS];
    int n = 0;
#pragma unroll
    for (int b = 0; b < BINS; b++) {
        counts[b] = g_cnt[b * CCOLS + c];
        n += (counts[b] >= 1) ? 1 : 0;
    }
    float nf = (float)max(n, 1);

#pragma unroll
    for (int b = 0; b < BINS; b++) {
        float accn = fmaf(0.25f, (float)counts[b], 0.75f * acc_sum[b * CCOLS + c]);
        g_wfac[b * CCOLS + c] = TOTF / (accn * nf);
    }
}

// ---------------------------------------------------------------- K3: weighted BCE sum
// Reads preds (64 MB) + packed target bits (2 MB) + wfac table (L2-resident).
__device__ __forceinline__ float elem_term(float p, int tbit, int c) {
    float t = (float)tbit;
    float s = p * fmaf(-2.0f, t, 1.0f);           // bce = softplus(s)
    int   b = bin_of_s(s);                        // identical math as K1
    float w = __ldg(&g_wfac[b * CCOLS + c]);      // 245 KB table, L2-resident
    float e   = __expf(-fabsf(s));
    float bce = fmaxf(s, 0.0f) + __logf(1.0f + e);
    return w * bce;
}

__global__ __launch_bounds__(256) void loss_kernel(const float4* __restrict__ preds,
                                                   float* __restrict__ out,
                                                   int nvec, float scale) {
    float acc = 0.0f;
    const int stride = gridDim.x * blockDim.x;
    for (int v = blockIdx.x * blockDim.x + threadIdx.x; v < nvec; v += stride) {
        float4 p = preds[v];
        int c = (v * 4) & (CCOLS - 1);            // 512 float4 per row
        int r = v >> 9;
        unsigned int w = g_bits[(size_t)r * (CCOLS / 32) + (c >> 5)];
        int sh_ = c & 31;                          // c%4==0 -> bits never straddle
        acc += elem_term(p.x, (w >> (sh_ + 0)) & 1, c + 0);
        acc += elem_term(p.y, (w >> (sh_ + 1)) & 1, c + 1);
        acc += elem_term(p.z, (w >> (sh_ + 2)) & 1, c + 2);
        acc += elem_term(p.w, (w >> (sh_ + 3)) & 1, c + 3);
    }
    // block reduction -> one atomic per block
#pragma unroll
    for (int o = 16; o > 0; o >>= 1) acc += __shfl_down_sync(0xffffffffu, acc, o);
    __shared__ float sw[8];
    int lane = threadIdx.x & 31, wid = threadIdx.x >> 5;
    if (lane == 0) sw[wid] = acc;
    __syncthreads();
    if (wid == 0) {
        acc = (lane < 8) ? sw[lane] : 0.0f;
#pragma unroll
        for (int o = 4; o > 0; o >>= 1) acc += __shfl_down_sync(0xffffffffu, acc, o);
        if (lane == 0) atomicAdd(out, acc * scale);
    }
}

// ---------------------------------------------------------------- launch
extern "C" void kernel_launch(void* const* d_in, const int* in_sizes, int n_in,
                              void* d_out, int out_size) {
    const float* preds   = (const float*)d_in[0];   // [8192, 2048] f32
    const int*   targets = (const int*)  d_in[1];   // [8192, 2048] i32
    const float* acc_sum = (const float*)d_in[2];   // [30, 2048]   f32
    float* out = (float*)d_out;                     // scalar loss

    // K1: count histogram + target bit-pack (16 col-tiles x 128 row-chunks = 2048 blocks)
    dim3 hgrid(CCOLS / TPB1, NROWS / RPB1);
    hist_kernel<<<hgrid, TPB1>>>(preds, targets);

    // K2a: chip-wide slab fold (120 blocks), zeroes out
    reduce_kernel<<<(NCELL / 2) / 256, 256>>>(out);

    // K2b: weight table from folded counts (tiny, L2-hot)
    wfac_kernel<<<CCOLS / 256, 256>>>(acc_sum);

    // K3: weighted BCE mean (preds + bit matrix)
    const int nvec = (NROWS * CCOLS) / 4;
    const float scale = 1.0f / ((float)NROWS * (float)CCOLS);  // LOSS_WEIGHT = 1
    loss_kernel<<<1184, 256>>>((const float4*)preds, out, nvec, scale);
}